// round 5
// baseline (speedup 1.0000x reference)
#include <cuda_runtime.h>

#define NC 8
#define NBINS 64
#define THREADS 256
#define WARPS_PER_BLOCK (THREADS / 32)
#define NUM_SMS 152

__global__ void cm_zero_kernel(float* __restrict__ out) {
    if (threadIdx.x < NBINS) out[threadIdx.x] = 0.0f;
}

__device__ __forceinline__ int argmax8(const float4 a, const float4 b) {
    float v[NC] = {a.x, a.y, a.z, a.w, b.x, b.y, b.z, b.w};
    int   idx = 0;
    float m   = v[0];
    // strict > keeps the first occurrence, matching jnp.argmax tie-break
    #pragma unroll
    for (int k = 1; k < NC; k++) {
        if (v[k] > m) { m = v[k]; idx = k; }
    }
    return idx;
}

__global__ __launch_bounds__(THREADS)
void cm_hist_kernel(const float4* __restrict__ yt,
                    const float4* __restrict__ yp,
                    float* __restrict__ out,
                    int n_rows) {
    // Per-warp private histograms: 8 warps x 64 bins of int (2 KB).
    __shared__ int hist[WARPS_PER_BLOCK * NBINS];

    const int wid = threadIdx.x >> 5;
    int* h = hist + wid * NBINS;

    for (int i = threadIdx.x; i < WARPS_PER_BLOCK * NBINS; i += THREADS)
        hist[i] = 0;
    __syncthreads();

    const int tid    = blockIdx.x * THREADS + threadIdx.x;
    const int stride = gridDim.x * THREADS;

    // 2 rows per iteration: 8 independent LDG.128 batched at the loop front
    // (higher MLP_eff hides the 577-cyc DRAM latency).
    int row = tid;
    for (; row + stride < n_rows; row += 2 * stride) {
        const int r0 = row;
        const int r1 = row + stride;

        const float4 t0a = yt[2 * r0 + 0];
        const float4 t0b = yt[2 * r0 + 1];
        const float4 p0a = yp[2 * r0 + 0];
        const float4 p0b = yp[2 * r0 + 1];
        const float4 t1a = yt[2 * r1 + 0];
        const float4 t1b = yt[2 * r1 + 1];
        const float4 p1a = yp[2 * r1 + 0];
        const float4 p1b = yp[2 * r1 + 1];

        const int ti0 = argmax8(t0a, t0b);
        const int pi0 = argmax8(p0a, p0b);
        const int ti1 = argmax8(t1a, t1b);
        const int pi1 = argmax8(p1a, p1b);

        atomicAdd(&h[ti0 * NC + pi0], 1);
        atomicAdd(&h[ti1 * NC + pi1], 1);
    }
    // Tail: at most one row left for this thread.
    if (row < n_rows) {
        const float4 ta = yt[2 * row + 0];
        const float4 tb = yt[2 * row + 1];
        const float4 pa = yp[2 * row + 0];
        const float4 pb = yp[2 * row + 1];
        atomicAdd(&h[argmax8(ta, tb) * NC + argmax8(pa, pb)], 1);
    }
    __syncthreads();

    // Reduce per-warp copies; one float atomic per bin per block.
    // Counts are integers < 2^24, so float accumulation is exact.
    for (int b = threadIdx.x; b < NBINS; b += THREADS) {
        int s = 0;
        #pragma unroll
        for (int w = 0; w < WARPS_PER_BLOCK; w++)
            s += hist[w * NBINS + b];
        if (s) atomicAdd(&out[b], (float)s);
    }
}

extern "C" void kernel_launch(void* const* d_in, const int* in_sizes, int n_in,
                              void* d_out, int out_size) {
    const float4* yt = (const float4*)d_in[0];   // y_true [N, 8] fp32
    const float4* yp = (const float4*)d_in[1];   // y_pred [N, 8] fp32
    float* out = (float*)d_out;                  // [8, 8] fp32

    const int n_rows = in_sizes[0] / NC;

    int blocks = NUM_SMS * 8;   // 8 CTAs/SM on 152 SMs
    int max_blocks = (n_rows + THREADS - 1) / THREADS;
    if (blocks > max_blocks) blocks = max_blocks;

    cm_zero_kernel<<<1, 64>>>(out);
    cm_hist_kernel<<<blocks, THREADS>>>(yt, yp, out, n_rows);
}

// round 6
// speedup vs baseline: 1.0281x; 1.0281x over previous
#include <cuda_runtime.h>

#define NC 8
#define NBINS 64
#define THREADS 256
#define WARPS_PER_BLOCK (THREADS / 32)
#define NUM_SMS 152

// Persistent device scratch (allocation-free). g_cm and g_count are zero at
// module load; the elected last block resets them to zero at the end of every
// run, so each graph replay sees identical initial state.
__device__ int g_cm[NBINS];
__device__ unsigned int g_count = 0;

__device__ __forceinline__ int argmax8(const float4 a, const float4 b) {
    float v[NC] = {a.x, a.y, a.z, a.w, b.x, b.y, b.z, b.w};
    int   idx = 0;
    float m   = v[0];
    // strict > keeps the first occurrence, matching jnp.argmax tie-break
    #pragma unroll
    for (int k = 1; k < NC; k++) {
        if (v[k] > m) { m = v[k]; idx = k; }
    }
    return idx;
}

__global__ __launch_bounds__(THREADS)
void cm_hist_kernel(const float4* __restrict__ yt,
                    const float4* __restrict__ yp,
                    float* __restrict__ out,
                    int n_rows) {
    // Per-warp private histograms: 8 warps x 64 bins of int (2 KB).
    __shared__ int hist[WARPS_PER_BLOCK * NBINS];
    __shared__ bool is_last;

    const int wid = threadIdx.x >> 5;
    int* h = hist + wid * NBINS;

    for (int i = threadIdx.x; i < WARPS_PER_BLOCK * NBINS; i += THREADS)
        hist[i] = 0;
    __syncthreads();

    const int tid    = blockIdx.x * THREADS + threadIdx.x;
    const int stride = gridDim.x * THREADS;

    // 2 rows per iteration: 8 independent LDG.128 batched at the loop front
    // (higher MLP_eff hides DRAM latency in the tail waves).
    int row = tid;
    for (; row + stride < n_rows; row += 2 * stride) {
        const int r0 = row;
        const int r1 = row + stride;

        const float4 t0a = yt[2 * r0 + 0];
        const float4 t0b = yt[2 * r0 + 1];
        const float4 p0a = yp[2 * r0 + 0];
        const float4 p0b = yp[2 * r0 + 1];
        const float4 t1a = yt[2 * r1 + 0];
        const float4 t1b = yt[2 * r1 + 1];
        const float4 p1a = yp[2 * r1 + 0];
        const float4 p1b = yp[2 * r1 + 1];

        const int ti0 = argmax8(t0a, t0b);
        const int pi0 = argmax8(p0a, p0b);
        const int ti1 = argmax8(t1a, t1b);
        const int pi1 = argmax8(p1a, p1b);

        atomicAdd(&h[ti0 * NC + pi0], 1);
        atomicAdd(&h[ti1 * NC + pi1], 1);
    }
    // Tail: at most one row left for this thread.
    if (row < n_rows) {
        const float4 ta = yt[2 * row + 0];
        const float4 tb = yt[2 * row + 1];
        const float4 pa = yp[2 * row + 0];
        const float4 pb = yp[2 * row + 1];
        atomicAdd(&h[argmax8(ta, tb) * NC + argmax8(pa, pb)], 1);
    }
    __syncthreads();

    // Reduce per-warp copies; one global int atomic per bin per block
    // (64 addresses x gridDim ops, hidden under the memory tail).
    for (int b = threadIdx.x; b < NBINS; b += THREADS) {
        int s = 0;
        #pragma unroll
        for (int w = 0; w < WARPS_PER_BLOCK; w++)
            s += hist[w * NBINS + b];
        if (s) atomicAdd(&g_cm[b], s);
    }

    // Grid-completion election (threadfence-reduction pattern): the last
    // block to finish converts the int histogram to float, writes d_out,
    // and resets scratch for the next graph replay.
    __threadfence();           // order this block's g_cm atomics before counter
    __syncthreads();
    if (threadIdx.x == 0) {
        unsigned int done = atomicAdd(&g_count, 1u);
        is_last = (done == gridDim.x - 1);
    }
    __syncthreads();

    if (is_last) {
        __threadfence();       // acquire: all blocks' g_cm updates visible
        if (threadIdx.x < NBINS) {
            const int b = threadIdx.x;
            // Counts are integers < 2^24, so float conversion is exact.
            out[b] = (float)g_cm[b];
            g_cm[b] = 0;       // reset scratch for next replay
        }
        __syncthreads();
        if (threadIdx.x == 0) g_count = 0;
    }
}

extern "C" void kernel_launch(void* const* d_in, const int* in_sizes, int n_in,
                              void* d_out, int out_size) {
    const float4* yt = (const float4*)d_in[0];   // y_true [N, 8] fp32
    const float4* yp = (const float4*)d_in[1];   // y_pred [N, 8] fp32
    float* out = (float*)d_out;                  // [8, 8] fp32

    const int n_rows = in_sizes[0] / NC;

    int blocks = NUM_SMS * 8;   // 8 CTAs/SM on 152 SMs
    int max_blocks = (n_rows + THREADS - 1) / THREADS;
    if (blocks > max_blocks) blocks = max_blocks;

    cm_hist_kernel<<<blocks, THREADS>>>(yt, yp, out, n_rows);
}